// round 13
// baseline (speedup 1.0000x reference)
#include <cuda_runtime.h>
#include <math.h>
#include <stdint.h>

#define HW 65536
#define CC 64
#define OO 64
#define BB 16
#define NQ 8
#define PIF 3.14159265358979323846f
#define NTILE (BB * (HW / 128))   // 8192 tiles of 128 px
#define GRID_CONV 592             // 4 CTAs/SM * 148 SMs

__device__ float g_xg[BB * NQ];
__device__ float g_part[BB * NQ * 4];
__device__ float g_add[BB * OO];
__device__ int   g_cnt;

// ---------------- helpers ----------------
__device__ __forceinline__ uint32_t cvt_tf32(float f) {
    uint32_t r; asm("cvt.rna.tf32.f32 %0, %1;" : "=r"(r) : "f"(f)); return r;
}
__device__ __forceinline__ void cp_async16(uint32_t s, const float* g) {
    asm volatile("cp.async.cg.shared.global [%0], [%1], 16;\n"
                 :: "r"(s), "l"(__cvta_generic_to_global(g)));
}
__device__ __forceinline__ void cp_commit() { asm volatile("cp.async.commit_group;\n"); }
template <int N> __device__ __forceinline__ void cp_wait() {
    asm volatile("cp.async.wait_group %0;\n" :: "n"(N));
}
__device__ __forceinline__ void mma8(float* c, const uint32_t* a, uint32_t b0, uint32_t b1) {
    asm volatile("mma.sync.aligned.m16n8k8.row.col.f32.tf32.tf32.f32 "
                 "{%0,%1,%2,%3}, {%4,%5,%6,%7}, {%8,%9}, {%0,%1,%2,%3};"
                 : "+f"(c[0]), "+f"(c[1]), "+f"(c[2]), "+f"(c[3])
                 : "r"(a[0]), "r"(a[1]), "r"(a[2]), "r"(a[3]), "r"(b0), "r"(b1));
}
__device__ __forceinline__ void stcs4(float* p, float4 v) {
    asm volatile("st.global.cs.v4.f32 [%0], {%1,%2,%3,%4};"
                 :: "l"(__cvta_generic_to_global(p)),
                    "f"(v.x), "f"(v.y), "f"(v.z), "f"(v.w));
}

// ============ K_PRE: 8-channel means (4-way split) + quantum + MLP =========
__global__ void k_pre(const float* __restrict__ x,
                      const float* __restrict__ cw, const float* __restrict__ qw,
                      const float* __restrict__ w1, const float* __restrict__ b1,
                      const float* __restrict__ w2, const float* __restrict__ b2,
                      const float* __restrict__ conv_b,
                      float* __restrict__ out, int out_size) {
    const int tid = threadIdx.x;
    const int cid = blockIdx.x >> 2;
    const int part = blockIdx.x & 3;
    const float4* p = reinterpret_cast<const float4*>(
        x + ((size_t)(cid >> 3) * CC + (cid & 7)) * HW + part * (HW / 4));
    float s = 0.0f;
    #pragma unroll 8
    for (int i = tid; i < HW / 16; i += 256) {
        float4 v = p[i];
        s += (v.x + v.y) + (v.z + v.w);
    }
    #pragma unroll
    for (int o = 16; o; o >>= 1) s += __shfl_xor_sync(0xffffffffu, s, o);
    __shared__ float ws[8];
    __shared__ int s_last;
    __shared__ float sh_h[BB][OO];
    if ((tid & 31) == 0) ws[tid >> 5] = s;
    __syncthreads();
    if (tid == 0) {
        float t = 0.0f;
        #pragma unroll
        for (int w = 0; w < 8; w++) t += ws[w];
        g_part[blockIdx.x] = t;
        __threadfence();
        s_last = (atomicAdd(&g_cnt, 1) == 4 * BB * NQ - 1) ? 1 : 0;
    }
    __syncthreads();
    if (!s_last) return;
    __threadfence();

    if (tid < BB * NQ) {
        float t = g_part[tid * 4] + g_part[tid * 4 + 1] +
                  g_part[tid * 4 + 2] + g_part[tid * 4 + 3];
        g_xg[tid] = t * (1.0f / (float)HW);
    }
    __syncthreads();

    const int wid = tid >> 5, lane = tid & 31;
    for (int rep = 0; rep < 2; rep++) {
        const int b = wid + rep * 8;
        float xq[NQ];
        #pragma unroll
        for (int pr = 0; pr < 4; pr++) {
            int ia = 2 * pr, ib = 2 * pr + 1;
            float ta = PIF * (g_xg[b * 8 + ia] * cw[ia]) + qw[ia];
            float tb = PIF * (g_xg[b * 8 + ib] * cw[ib]) + qw[ib];
            float sa, ca, sb, cb;
            sincosf(ta * 0.5f, &sa, &ca);
            sincosf(tb * 0.5f, &sb, &cb);
            float psi00 = ca * cb, psi01 = ca * sb, psi10 = sa * sb, psi11 = sa * cb;
            float shA, chA, shB, chB;
            sincosf(qw[8 + ia] * 0.5f, &shA, &chA);
            sincosf(qw[8 + ib] * 0.5f, &shB, &chB);
            float m00 = chA * psi00 - shA * psi10, m01 = chA * psi01 - shA * psi11;
            float m10 = shA * psi00 + chA * psi10, m11 = shA * psi01 + chA * psi11;
            float q00 = m00 * chB - m01 * shB, q01 = m00 * shB + m01 * chB;
            float q10 = m10 * chB - m11 * shB, q11 = m10 * shB + m11 * chB;
            float p00 = q00 * q00, p01 = q01 * q01, p10 = q10 * q10, p11 = q11 * q11;
            xq[ia] = (p00 + p01) - (p10 + p11);
            xq[ib] = (p00 + p10) - (p01 + p11);
        }
        float ss = 0.0f;
        #pragma unroll
        for (int i = 0; i < NQ; i++) ss += xq[i] * xq[i];
        float strength = sqrtf(ss);
        float gate = 1.0f / (1.0f + expf(-(strength - 0.05f)));

        #pragma unroll
        for (int r2 = 0; r2 < 2; r2++) {
            int j = lane + r2 * 32;
            float hv = b1[j];
            #pragma unroll
            for (int i = 0; i < NQ; i++) hv += xq[i] * w1[j * NQ + i];
            sh_h[b][j] = fmaxf(hv, 0.0f);
        }
        __syncwarp();
        #pragma unroll
        for (int r2 = 0; r2 < 2; r2++) {
            int o = lane + r2 * 32;
            float gv = b2[o];
            #pragma unroll 8
            for (int j = 0; j < OO; j++) gv += sh_h[b][j] * w2[o * OO + j];
            g_add[b * OO + o] = conv_b[o] + gate * gv;
        }
        const long long base = (long long)BB * OO * HW;
        if ((long long)out_size >= base + BB * NQ + BB) {
            if (lane < NQ) out[base + b * NQ + lane] = xq[lane];
            if (lane == 0) out[base + BB * NQ + b] = strength;
        }
    }
    __syncthreads();
    if (tid == 0) g_cnt = 0;
}

// ============ K_CONV: persistent tf32 mma.sync GEMM, 2Mx4N warps ===========
// Tile = 64 o x 128 px. A-pairs packed adjacent -> LDS.64. 3-slot ring.
// Epilogue: shfl-widened float4 streaming stores.
#define SM_W   0
#define SM_STG 18432                       // 64 * 72 * 4
#define SLOT_B 8704                        // 16 * 136 * 4
#define SM_SZ  (SM_STG + 3 * SLOT_B)       // 44544 B

__global__ void __launch_bounds__(256, 4)
k_conv(const float* __restrict__ x, const float* __restrict__ conv_w,
       float* __restrict__ out) {
    extern __shared__ __align__(16) char sm[];
    uint32_t* whi = (uint32_t*)(sm + SM_W);     // [o][72], c permuted pair-adjacent
    float*    stg = (float*)(sm + SM_STG);
    const uint32_t stg_b = (uint32_t)__cvta_generic_to_shared(sm) + SM_STG;

    const int tid = threadIdx.x, lane = tid & 31, wid = tid >> 5;
    const int wm = wid & 1, wn = wid >> 1;     // 2 M-groups, 4 N-groups
    const int g = lane >> 2, tig = lane & 3;
    const int m0 = wm * 32;

    auto prefetch = [&](int m, int slot) {
        int t = blockIdx.x + (m >> 2) * gridDim.x;
        if (t < NTILE) {
            int b = t >> 9, px0 = (t & 511) << 7, kc = m & 3;
            const float* src = x + ((size_t)b * CC + kc * 16) * HW + px0;
            #pragma unroll
            for (int it = 0; it < 2; it++) {
                int e = tid + it * 256;
                int row = e >> 5, quad = e & 31;
                cp_async16(stg_b + (uint32_t)(slot * SLOT_B + row * 544 + quad * 16),
                           src + (size_t)row * HW + quad * 4);
            }
        }
        cp_commit();
    };

    prefetch(0, 0);
    prefetch(1, 1);

    // weight fill, permuted so A pairs (c, c+4) land adjacent:
    // c -> kc*16 + ks*8 + tig*2 + half   (kc=c>>4, ks=(c>>3)&1, tig=c&3, half=(c>>2)&1)
    for (int e = tid; e < OO * CC; e += 256) {
        int o = e >> 6, c = e & 63;
        int cp = (c & 0x30) | ((c & 8)) | ((c & 3) << 1) | ((c >> 2) & 1);
        whi[o * 72 + cp] = cvt_tf32(conv_w[o * CC + c]);
    }
    __syncthreads();

    int cn = 0;
    for (int t = blockIdx.x; t < NTILE; t += gridDim.x) {
        float acc[2][4][4];
        #pragma unroll
        for (int m = 0; m < 2; m++)
            #pragma unroll
            for (int j = 0; j < 4; j++)
                #pragma unroll
                for (int v = 0; v < 4; v++) acc[m][j][v] = 0.0f;

        #pragma unroll 1
        for (int kc = 0; kc < 4; kc++, cn++) {
            cp_wait<1>();             // chunk cn complete
            __syncthreads();          // slot (cn+2)%3 fully consumed by all
            prefetch(cn + 2, (cn + 2) % 3);

            const float* xs = stg + (cn % 3) * (SLOT_B / 4);
            #pragma unroll
            for (int ks = 0; ks < 2; ks++) {
                const int ab = kc * 16 + ks * 8 + tig * 2;
                uint2 p0 = *(const uint2*)&whi[(m0 + g) * 72 + ab];
                uint2 p1 = *(const uint2*)&whi[(m0 + g + 8) * 72 + ab];
                uint2 p2 = *(const uint2*)&whi[(m0 + 16 + g) * 72 + ab];
                uint2 p3 = *(const uint2*)&whi[(m0 + 24 + g) * 72 + ab];
                uint32_t a[8] = {p0.x, p1.x, p0.y, p1.y, p2.x, p3.x, p2.y, p3.y};
                const int r0 = ks * 8 + tig;
                #pragma unroll
                for (int j = 0; j < 4; j++) {
                    int col = wn * 32 + j * 8 + g;
                    uint32_t b0 = cvt_tf32(xs[r0 * 136 + col]);
                    uint32_t b1 = cvt_tf32(xs[(r0 + 4) * 136 + col]);
                    mma8(acc[0][j], a, b0, b1);
                    mma8(acc[1][j], a + 4, b0, b1);
                }
            }
        }

        // ---- epilogue: shfl.xor(1) pairs tig-neighbors into float4 stores ----
        const int b = t >> 9, px0 = (t & 511) << 7;
        const int todd = tig & 1;
        #pragma unroll
        for (int m = 0; m < 2; m++) {
            const int orow = m0 + m * 16;
            #pragma unroll
            for (int half = 0; half < 2; half++) {
                float add = g_add[b * OO + orow + half * 8 + g];
                float* rp = out + ((size_t)(b * OO + orow + half * 8 + g)) * HW
                                + px0 + wn * 32;
                const int v0 = half * 2;
                #pragma unroll
                for (int jp = 0; jp < 4; jp += 2) {
                    float2 a0 = make_float2(acc[m][jp][v0] + add,
                                            acc[m][jp][v0 + 1] + add);
                    float2 a1 = make_float2(acc[m][jp + 1][v0] + add,
                                            acc[m][jp + 1][v0 + 1] + add);
                    float2 give = todd ? a0 : a1;
                    float2 keep = todd ? a1 : a0;
                    float2 recv;
                    recv.x = __shfl_xor_sync(0xffffffffu, give.x, 1);
                    recv.y = __shfl_xor_sync(0xffffffffu, give.y, 1);
                    float4 v = todd ? make_float4(recv.x, recv.y, keep.x, keep.y)
                                    : make_float4(keep.x, keep.y, recv.x, recv.y);
                    int C = 8 * (jp + todd) + 4 * (tig >> 1);
                    stcs4(rp + C, v);
                }
            }
        }
    }
}

// ================= launch =================================================
extern "C" void kernel_launch(void* const* d_in, const int* in_sizes, int n_in,
                              void* d_out, int out_size) {
    const float* x      = (const float*)d_in[0];
    const float* cw     = (const float*)d_in[1];
    const float* qw     = (const float*)d_in[2];
    const float* w1     = (const float*)d_in[3];
    const float* b1     = (const float*)d_in[4];
    const float* w2     = (const float*)d_in[5];
    const float* b2     = (const float*)d_in[6];
    const float* conv_w = (const float*)d_in[7];
    const float* conv_b = (const float*)d_in[8];
    float* out = (float*)d_out;

    cudaFuncSetAttribute(k_conv, cudaFuncAttributeMaxDynamicSharedMemorySize, SM_SZ);
    k_pre<<<BB * NQ * 4, 256>>>(x, cw, qw, w1, b1, w2, b2, conv_b, out, out_size);
    k_conv<<<GRID_CONV, 256, SM_SZ>>>(x, conv_w, out);
}

// round 14
// speedup vs baseline: 1.0390x; 1.0390x over previous
#include <cuda_runtime.h>
#include <math.h>
#include <stdint.h>

#define HW 65536
#define CC 64
#define OO 64
#define BB 16
#define NQ 8
#define PIF 3.14159265358979323846f
#define NTILE (BB * (HW / 128))   // 8192 tiles of 128 px
#define GRID_CONV 592             // 4 CTAs/SM * 148 SMs

__device__ float g_xg[BB * NQ];
__device__ float g_part[BB * NQ * 4];
__device__ float g_add[BB * OO];
__device__ int   g_cnt;

// ---------------- helpers ----------------
__device__ __forceinline__ uint32_t cvt_tf32(float f) {
    uint32_t r; asm("cvt.rna.tf32.f32 %0, %1;" : "=r"(r) : "f"(f)); return r;
}
__device__ __forceinline__ void cp_async16(uint32_t s, const float* g) {
    asm volatile("cp.async.cg.shared.global [%0], [%1], 16;\n"
                 :: "r"(s), "l"(__cvta_generic_to_global(g)));
}
__device__ __forceinline__ void cp_commit() { asm volatile("cp.async.commit_group;\n"); }
template <int N> __device__ __forceinline__ void cp_wait() {
    asm volatile("cp.async.wait_group %0;\n" :: "n"(N));
}
__device__ __forceinline__ void mma8(float* c, const uint32_t* a, uint32_t b0, uint32_t b1) {
    asm volatile("mma.sync.aligned.m16n8k8.row.col.f32.tf32.tf32.f32 "
                 "{%0,%1,%2,%3}, {%4,%5,%6,%7}, {%8,%9}, {%0,%1,%2,%3};"
                 : "+f"(c[0]), "+f"(c[1]), "+f"(c[2]), "+f"(c[3])
                 : "r"(a[0]), "r"(a[1]), "r"(a[2]), "r"(a[3]), "r"(b0), "r"(b1));
}

// ============ K_PRE: 8-channel means (4-way split) + quantum + MLP =========
__global__ void k_pre(const float* __restrict__ x,
                      const float* __restrict__ cw, const float* __restrict__ qw,
                      const float* __restrict__ w1, const float* __restrict__ b1,
                      const float* __restrict__ w2, const float* __restrict__ b2,
                      const float* __restrict__ conv_b,
                      float* __restrict__ out, int out_size) {
    const int tid = threadIdx.x;
    const int cid = blockIdx.x >> 2;
    const int part = blockIdx.x & 3;
    const float4* p = reinterpret_cast<const float4*>(
        x + ((size_t)(cid >> 3) * CC + (cid & 7)) * HW + part * (HW / 4));
    float s = 0.0f;
    #pragma unroll 8
    for (int i = tid; i < HW / 16; i += 256) {
        float4 v = p[i];
        s += (v.x + v.y) + (v.z + v.w);
    }
    #pragma unroll
    for (int o = 16; o; o >>= 1) s += __shfl_xor_sync(0xffffffffu, s, o);
    __shared__ float ws[8];
    __shared__ int s_last;
    __shared__ float sh_h[BB][OO];
    if ((tid & 31) == 0) ws[tid >> 5] = s;
    __syncthreads();
    if (tid == 0) {
        float t = 0.0f;
        #pragma unroll
        for (int w = 0; w < 8; w++) t += ws[w];
        g_part[blockIdx.x] = t;
        __threadfence();
        s_last = (atomicAdd(&g_cnt, 1) == 4 * BB * NQ - 1) ? 1 : 0;
    }
    __syncthreads();
    if (!s_last) return;
    __threadfence();

    if (tid < BB * NQ) {
        float t = g_part[tid * 4] + g_part[tid * 4 + 1] +
                  g_part[tid * 4 + 2] + g_part[tid * 4 + 3];
        g_xg[tid] = t * (1.0f / (float)HW);
    }
    __syncthreads();

    const int wid = tid >> 5, lane = tid & 31;
    for (int rep = 0; rep < 2; rep++) {
        const int b = wid + rep * 8;
        float xq[NQ];
        #pragma unroll
        for (int pr = 0; pr < 4; pr++) {
            int ia = 2 * pr, ib = 2 * pr + 1;
            float ta = PIF * (g_xg[b * 8 + ia] * cw[ia]) + qw[ia];
            float tb = PIF * (g_xg[b * 8 + ib] * cw[ib]) + qw[ib];
            float sa, ca, sb, cb;
            sincosf(ta * 0.5f, &sa, &ca);
            sincosf(tb * 0.5f, &sb, &cb);
            float psi00 = ca * cb, psi01 = ca * sb, psi10 = sa * sb, psi11 = sa * cb;
            float shA, chA, shB, chB;
            sincosf(qw[8 + ia] * 0.5f, &shA, &chA);
            sincosf(qw[8 + ib] * 0.5f, &shB, &chB);
            float m00 = chA * psi00 - shA * psi10, m01 = chA * psi01 - shA * psi11;
            float m10 = shA * psi00 + chA * psi10, m11 = shA * psi01 + chA * psi11;
            float q00 = m00 * chB - m01 * shB, q01 = m00 * shB + m01 * chB;
            float q10 = m10 * chB - m11 * shB, q11 = m10 * shB + m11 * chB;
            float p00 = q00 * q00, p01 = q01 * q01, p10 = q10 * q10, p11 = q11 * q11;
            xq[ia] = (p00 + p01) - (p10 + p11);
            xq[ib] = (p00 + p10) - (p01 + p11);
        }
        float ss = 0.0f;
        #pragma unroll
        for (int i = 0; i < NQ; i++) ss += xq[i] * xq[i];
        float strength = sqrtf(ss);
        float gate = 1.0f / (1.0f + expf(-(strength - 0.05f)));

        #pragma unroll
        for (int r2 = 0; r2 < 2; r2++) {
            int j = lane + r2 * 32;
            float hv = b1[j];
            #pragma unroll
            for (int i = 0; i < NQ; i++) hv += xq[i] * w1[j * NQ + i];
            sh_h[b][j] = fmaxf(hv, 0.0f);
        }
        __syncwarp();
        #pragma unroll
        for (int r2 = 0; r2 < 2; r2++) {
            int o = lane + r2 * 32;
            float gv = b2[o];
            #pragma unroll 8
            for (int j = 0; j < OO; j++) gv += sh_h[b][j] * w2[o * OO + j];
            g_add[b * OO + o] = conv_b[o] + gate * gv;
        }
        const long long base = (long long)BB * OO * HW;
        if ((long long)out_size >= base + BB * NQ + BB) {
            if (lane < NQ) out[base + b * NQ + lane] = xq[lane];
            if (lane == 0) out[base + BB * NQ + b] = strength;
        }
    }
    __syncthreads();
    if (tid == 0) g_cnt = 0;
}

// ============ K_CONV: persistent tf32 mma.sync GEMM, 2Mx4N warps ===========
// Tile = 64 o x 128 px. 8 warps = 2(M: 32 o) x 4(N: 32 px). 3-slot ring.
// Epilogue: shfl-widened float4 streaming (__stcs) stores.
#define SM_W   0
#define SM_STG 17408                       // 64 * 68 * 4
#define SLOT_B 8704                        // 16 * 136 * 4
#define SM_SZ  (SM_STG + 3 * SLOT_B)       // 43520 B

__global__ void __launch_bounds__(256, 4)
k_conv(const float* __restrict__ x, const float* __restrict__ conv_w,
       float* __restrict__ out) {
    extern __shared__ __align__(16) char sm[];
    uint32_t* whi = (uint32_t*)(sm + SM_W);
    float*    stg = (float*)(sm + SM_STG);
    const uint32_t stg_b = (uint32_t)__cvta_generic_to_shared(sm) + SM_STG;

    const int tid = threadIdx.x, lane = tid & 31, wid = tid >> 5;
    const int wm = wid & 1, wn = wid >> 1;     // 2 M-groups, 4 N-groups
    const int g = lane >> 2, tig = lane & 3;
    const int m0 = wm * 32;

    auto prefetch = [&](int m, int slot) {
        int t = blockIdx.x + (m >> 2) * gridDim.x;
        if (t < NTILE) {
            int b = t >> 9, px0 = (t & 511) << 7, kc = m & 3;
            const float* src = x + ((size_t)b * CC + kc * 16) * HW + px0;
            #pragma unroll
            for (int it = 0; it < 2; it++) {
                int e = tid + it * 256;
                int row = e >> 5, quad = e & 31;
                cp_async16(stg_b + (uint32_t)(slot * SLOT_B + row * 544 + quad * 16),
                           src + (size_t)row * HW + quad * 4);
            }
        }
        cp_commit();
    };

    prefetch(0, 0);
    prefetch(1, 1);

    for (int e = tid; e < OO * CC; e += 256) {
        int o = e >> 6, c = e & 63;
        whi[o * 68 + c] = cvt_tf32(conv_w[o * CC + c]);
    }
    __syncthreads();

    int cn = 0;
    for (int t = blockIdx.x; t < NTILE; t += gridDim.x) {
        float acc[2][4][4];
        #pragma unroll
        for (int m = 0; m < 2; m++)
            #pragma unroll
            for (int j = 0; j < 4; j++)
                #pragma unroll
                for (int v = 0; v < 4; v++) acc[m][j][v] = 0.0f;

        #pragma unroll 1
        for (int kc = 0; kc < 4; kc++, cn++) {
            cp_wait<1>();             // chunk cn complete
            __syncthreads();          // slot (cn+2)%3 fully consumed by all
            prefetch(cn + 2, (cn + 2) % 3);

            const float* xs = stg + (cn % 3) * (SLOT_B / 4);
            #pragma unroll
            for (int ks = 0; ks < 2; ks++) {
                const int c0 = kc * 16 + ks * 8 + tig;
                uint32_t a[8];
                a[0] = whi[(m0 + g) * 68 + c0];
                a[1] = whi[(m0 + g + 8) * 68 + c0];
                a[2] = whi[(m0 + g) * 68 + c0 + 4];
                a[3] = whi[(m0 + g + 8) * 68 + c0 + 4];
                a[4] = whi[(m0 + 16 + g) * 68 + c0];
                a[5] = whi[(m0 + 24 + g) * 68 + c0];
                a[6] = whi[(m0 + 16 + g) * 68 + c0 + 4];
                a[7] = whi[(m0 + 24 + g) * 68 + c0 + 4];
                const int r0 = ks * 8 + tig;
                #pragma unroll
                for (int j = 0; j < 4; j++) {
                    int col = wn * 32 + j * 8 + g;
                    uint32_t b0 = cvt_tf32(xs[r0 * 136 + col]);
                    uint32_t b1 = cvt_tf32(xs[(r0 + 4) * 136 + col]);
                    mma8(acc[0][j], a, b0, b1);
                    mma8(acc[1][j], a + 4, b0, b1);
                }
            }
        }

        // ---- epilogue: shfl.xor(1) pairs tig-neighbors into float4 stores ----
        const int b = t >> 9, px0 = (t & 511) << 7;
        const int todd = tig & 1;
        #pragma unroll
        for (int m = 0; m < 2; m++) {
            const int orow = m0 + m * 16;
            #pragma unroll
            for (int half = 0; half < 2; half++) {
                float add = g_add[b * OO + orow + half * 8 + g];
                float* rp = out + ((size_t)(b * OO + orow + half * 8 + g)) * HW
                                + px0 + wn * 32;
                const int v0 = half * 2;
                #pragma unroll
                for (int jp = 0; jp < 4; jp += 2) {
                    float2 a0 = make_float2(acc[m][jp][v0] + add,
                                            acc[m][jp][v0 + 1] + add);
                    float2 a1 = make_float2(acc[m][jp + 1][v0] + add,
                                            acc[m][jp + 1][v0 + 1] + add);
                    float2 give = todd ? a0 : a1;
                    float2 keep = todd ? a1 : a0;
                    float2 recv;
                    recv.x = __shfl_xor_sync(0xffffffffu, give.x, 1);
                    recv.y = __shfl_xor_sync(0xffffffffu, give.y, 1);
                    float4 v = todd ? make_float4(recv.x, recv.y, keep.x, keep.y)
                                    : make_float4(keep.x, keep.y, recv.x, recv.y);
                    int C = 8 * (jp + todd) + 4 * (tig >> 1);
                    __stcs((float4*)(rp + C), v);
                }
            }
        }
    }
}

// ================= launch =================================================
extern "C" void kernel_launch(void* const* d_in, const int* in_sizes, int n_in,
                              void* d_out, int out_size) {
    const float* x      = (const float*)d_in[0];
    const float* cw     = (const float*)d_in[1];
    const float* qw     = (const float*)d_in[2];
    const float* w1     = (const float*)d_in[3];
    const float* b1     = (const float*)d_in[4];
    const float* w2     = (const float*)d_in[5];
    const float* b2     = (const float*)d_in[6];
    const float* conv_w = (const float*)d_in[7];
    const float* conv_b = (const float*)d_in[8];
    float* out = (float*)d_out;

    cudaFuncSetAttribute(k_conv, cudaFuncAttributeMaxDynamicSharedMemorySize, SM_SZ);
    k_pre<<<BB * NQ * 4, 256>>>(x, cw, qw, w1, b1, w2, b2, conv_b, out, out_size);
    k_conv<<<GRID_CONV, 256, SM_SZ>>>(x, conv_w, out);
}

// round 15
// speedup vs baseline: 1.0464x; 1.0072x over previous
#include <cuda_runtime.h>
#include <math.h>
#include <stdint.h>

#define HW 65536
#define CC 64
#define OO 64
#define BB 16
#define NQ 8
#define PIF 3.14159265358979323846f
#define NTILE (BB * (HW / 256))   // 4096 tiles of 256 px
#define GRID_CONV 296             // 2 CTAs/SM * 148 SMs

__device__ float g_xg[BB * NQ];
__device__ float g_part[BB * NQ * 4];
__device__ float g_add[BB * OO];
__device__ int   g_cnt;

// ---------------- helpers ----------------
__device__ __forceinline__ uint32_t cvt_tf32(float f) {
    uint32_t r; asm("cvt.rna.tf32.f32 %0, %1;" : "=r"(r) : "f"(f)); return r;
}
__device__ __forceinline__ void cp_async16(uint32_t s, const float* g) {
    asm volatile("cp.async.cg.shared.global [%0], [%1], 16;\n"
                 :: "r"(s), "l"(__cvta_generic_to_global(g)));
}
__device__ __forceinline__ void cp_commit() { asm volatile("cp.async.commit_group;\n"); }
template <int N> __device__ __forceinline__ void cp_wait() {
    asm volatile("cp.async.wait_group %0;\n" :: "n"(N));
}
__device__ __forceinline__ void mma8(float* c, const uint32_t* a, uint32_t b0, uint32_t b1) {
    asm volatile("mma.sync.aligned.m16n8k8.row.col.f32.tf32.tf32.f32 "
                 "{%0,%1,%2,%3}, {%4,%5,%6,%7}, {%8,%9}, {%0,%1,%2,%3};"
                 : "+f"(c[0]), "+f"(c[1]), "+f"(c[2]), "+f"(c[3])
                 : "r"(a[0]), "r"(a[1]), "r"(a[2]), "r"(a[3]), "r"(b0), "r"(b1));
}

// ============ K_PRE: 8-channel means (4-way split) + quantum + MLP =========
__global__ void k_pre(const float* __restrict__ x,
                      const float* __restrict__ cw, const float* __restrict__ qw,
                      const float* __restrict__ w1, const float* __restrict__ b1,
                      const float* __restrict__ w2, const float* __restrict__ b2,
                      const float* __restrict__ conv_b,
                      float* __restrict__ out, int out_size) {
    const int tid = threadIdx.x;
    const int cid = blockIdx.x >> 2;
    const int part = blockIdx.x & 3;
    const float4* p = reinterpret_cast<const float4*>(
        x + ((size_t)(cid >> 3) * CC + (cid & 7)) * HW + part * (HW / 4));
    float s = 0.0f;
    #pragma unroll 8
    for (int i = tid; i < HW / 16; i += 256) {
        float4 v = p[i];
        s += (v.x + v.y) + (v.z + v.w);
    }
    #pragma unroll
    for (int o = 16; o; o >>= 1) s += __shfl_xor_sync(0xffffffffu, s, o);
    __shared__ float ws[8];
    __shared__ int s_last;
    __shared__ float sh_h[BB][OO];
    if ((tid & 31) == 0) ws[tid >> 5] = s;
    __syncthreads();
    if (tid == 0) {
        float t = 0.0f;
        #pragma unroll
        for (int w = 0; w < 8; w++) t += ws[w];
        g_part[blockIdx.x] = t;
        __threadfence();
        s_last = (atomicAdd(&g_cnt, 1) == 4 * BB * NQ - 1) ? 1 : 0;
    }
    __syncthreads();
    if (!s_last) return;
    __threadfence();

    if (tid < BB * NQ) {
        float t = g_part[tid * 4] + g_part[tid * 4 + 1] +
                  g_part[tid * 4 + 2] + g_part[tid * 4 + 3];
        g_xg[tid] = t * (1.0f / (float)HW);
    }
    __syncthreads();

    const int wid = tid >> 5, lane = tid & 31;
    for (int rep = 0; rep < 2; rep++) {
        const int b = wid + rep * 8;
        float xq[NQ];
        #pragma unroll
        for (int pr = 0; pr < 4; pr++) {
            int ia = 2 * pr, ib = 2 * pr + 1;
            float ta = PIF * (g_xg[b * 8 + ia] * cw[ia]) + qw[ia];
            float tb = PIF * (g_xg[b * 8 + ib] * cw[ib]) + qw[ib];
            float sa, ca, sb, cb;
            sincosf(ta * 0.5f, &sa, &ca);
            sincosf(tb * 0.5f, &sb, &cb);
            float psi00 = ca * cb, psi01 = ca * sb, psi10 = sa * sb, psi11 = sa * cb;
            float shA, chA, shB, chB;
            sincosf(qw[8 + ia] * 0.5f, &shA, &chA);
            sincosf(qw[8 + ib] * 0.5f, &shB, &chB);
            float m00 = chA * psi00 - shA * psi10, m01 = chA * psi01 - shA * psi11;
            float m10 = shA * psi00 + chA * psi10, m11 = shA * psi01 + chA * psi11;
            float q00 = m00 * chB - m01 * shB, q01 = m00 * shB + m01 * chB;
            float q10 = m10 * chB - m11 * shB, q11 = m10 * shB + m11 * chB;
            float p00 = q00 * q00, p01 = q01 * q01, p10 = q10 * q10, p11 = q11 * q11;
            xq[ia] = (p00 + p01) - (p10 + p11);
            xq[ib] = (p00 + p10) - (p01 + p11);
        }
        float ss = 0.0f;
        #pragma unroll
        for (int i = 0; i < NQ; i++) ss += xq[i] * xq[i];
        float strength = sqrtf(ss);
        float gate = 1.0f / (1.0f + expf(-(strength - 0.05f)));

        #pragma unroll
        for (int r2 = 0; r2 < 2; r2++) {
            int j = lane + r2 * 32;
            float hv = b1[j];
            #pragma unroll
            for (int i = 0; i < NQ; i++) hv += xq[i] * w1[j * NQ + i];
            sh_h[b][j] = fmaxf(hv, 0.0f);
        }
        __syncwarp();
        #pragma unroll
        for (int r2 = 0; r2 < 2; r2++) {
            int o = lane + r2 * 32;
            float gv = b2[o];
            #pragma unroll 8
            for (int j = 0; j < OO; j++) gv += sh_h[b][j] * w2[o * OO + j];
            g_add[b * OO + o] = conv_b[o] + gate * gv;
        }
        const long long base = (long long)BB * OO * HW;
        if ((long long)out_size >= base + BB * NQ + BB) {
            if (lane < NQ) out[base + b * NQ + lane] = xq[lane];
            if (lane == 0) out[base + BB * NQ + b] = strength;
        }
    }
    __syncthreads();
    if (tid == 0) g_cnt = 0;
}

// ============ K_CONV: persistent tf32 mma.sync GEMM, 512 thr, 2Mx8N =======
// Tile = 64 o x 256 px. 16 warps = 2(M: 32 o) x 8(N: 32 px). 3-slot ring.
// Per-thread mainloop identical to the 256-thr version; chunk = 16c x 256px.
#define SM_W   0
#define SM_STG 17408                       // 64 * 68 * 4
#define SLOT_B 16896                       // 16 * 264 * 4
#define SM_SZ  (SM_STG + 3 * SLOT_B)       // 68096 B

__global__ void __launch_bounds__(512, 2)
k_conv(const float* __restrict__ x, const float* __restrict__ conv_w,
       float* __restrict__ out) {
    extern __shared__ __align__(16) char sm[];
    uint32_t* whi = (uint32_t*)(sm + SM_W);
    float*    stg = (float*)(sm + SM_STG);
    const uint32_t stg_b = (uint32_t)__cvta_generic_to_shared(sm) + SM_STG;

    const int tid = threadIdx.x, lane = tid & 31, wid = tid >> 5;
    const int wm = wid & 1, wn = wid >> 1;     // 2 M-groups, 8 N-groups
    const int g = lane >> 2, tig = lane & 3;
    const int m0 = wm * 32;

    auto prefetch = [&](int m, int slot) {
        int t = blockIdx.x + (m >> 2) * gridDim.x;
        if (t < NTILE) {
            int b = t >> 8, px0 = (t & 255) << 8, kc = m & 3;
            const float* src = x + ((size_t)b * CC + kc * 16) * HW + px0;
            #pragma unroll
            for (int it = 0; it < 2; it++) {
                int e = tid + it * 512;
                int row = e >> 6, quad = e & 63;
                cp_async16(stg_b + (uint32_t)(slot * SLOT_B + row * 1056 + quad * 16),
                           src + (size_t)row * HW + quad * 4);
            }
        }
        cp_commit();
    };

    prefetch(0, 0);
    prefetch(1, 1);

    for (int e = tid; e < OO * CC; e += 512) {
        int o = e >> 6, c = e & 63;
        whi[o * 68 + c] = cvt_tf32(conv_w[o * CC + c]);
    }
    __syncthreads();

    int cn = 0;
    for (int t = blockIdx.x; t < NTILE; t += gridDim.x) {
        float acc[2][4][4];
        #pragma unroll
        for (int m = 0; m < 2; m++)
            #pragma unroll
            for (int j = 0; j < 4; j++)
                #pragma unroll
                for (int v = 0; v < 4; v++) acc[m][j][v] = 0.0f;

        #pragma unroll 1
        for (int kc = 0; kc < 4; kc++, cn++) {
            cp_wait<1>();             // chunk cn complete
            __syncthreads();          // slot (cn+2)%3 fully consumed by all
            prefetch(cn + 2, (cn + 2) % 3);

            const float* xs = stg + (cn % 3) * (SLOT_B / 4);
            #pragma unroll
            for (int ks = 0; ks < 2; ks++) {
                const int c0 = kc * 16 + ks * 8 + tig;
                uint32_t a[8];
                a[0] = whi[(m0 + g) * 68 + c0];
                a[1] = whi[(m0 + g + 8) * 68 + c0];
                a[2] = whi[(m0 + g) * 68 + c0 + 4];
                a[3] = whi[(m0 + g + 8) * 68 + c0 + 4];
                a[4] = whi[(m0 + 16 + g) * 68 + c0];
                a[5] = whi[(m0 + 24 + g) * 68 + c0];
                a[6] = whi[(m0 + 16 + g) * 68 + c0 + 4];
                a[7] = whi[(m0 + 24 + g) * 68 + c0 + 4];
                const int r0 = ks * 8 + tig;
                #pragma unroll
                for (int j = 0; j < 4; j++) {
                    int col = wn * 32 + j * 8 + g;
                    uint32_t b0 = cvt_tf32(xs[r0 * 264 + col]);
                    uint32_t b1 = cvt_tf32(xs[(r0 + 4) * 264 + col]);
                    mma8(acc[0][j], a, b0, b1);
                    mma8(acc[1][j], a + 4, b0, b1);
                }
            }
        }

        // ---- epilogue: shfl.xor(1) pairs tig-neighbors into float4 stores ----
        const int b = t >> 8, px0 = (t & 255) << 8;
        const int todd = tig & 1;
        #pragma unroll
        for (int m = 0; m < 2; m++) {
            const int orow = m0 + m * 16;
            #pragma unroll
            for (int half = 0; half < 2; half++) {
                float add = g_add[b * OO + orow + half * 8 + g];
                float* rp = out + ((size_t)(b * OO + orow + half * 8 + g)) * HW
                                + px0 + wn * 32;
                const int v0 = half * 2;
                #pragma unroll
                for (int jp = 0; jp < 4; jp += 2) {
                    float2 a0 = make_float2(acc[m][jp][v0] + add,
                                            acc[m][jp][v0 + 1] + add);
                    float2 a1 = make_float2(acc[m][jp + 1][v0] + add,
                                            acc[m][jp + 1][v0 + 1] + add);
                    float2 give = todd ? a0 : a1;
                    float2 keep = todd ? a1 : a0;
                    float2 recv;
                    recv.x = __shfl_xor_sync(0xffffffffu, give.x, 1);
                    recv.y = __shfl_xor_sync(0xffffffffu, give.y, 1);
                    float4 v = todd ? make_float4(recv.x, recv.y, keep.x, keep.y)
                                    : make_float4(keep.x, keep.y, recv.x, recv.y);
                    int C = 8 * (jp + todd) + 4 * (tig >> 1);
                    __stcs((float4*)(rp + C), v);
                }
            }
        }
    }
}

// ================= launch =================================================
extern "C" void kernel_launch(void* const* d_in, const int* in_sizes, int n_in,
                              void* d_out, int out_size) {
    const float* x      = (const float*)d_in[0];
    const float* cw     = (const float*)d_in[1];
    const float* qw     = (const float*)d_in[2];
    const float* w1     = (const float*)d_in[3];
    const float* b1     = (const float*)d_in[4];
    const float* w2     = (const float*)d_in[5];
    const float* b2     = (const float*)d_in[6];
    const float* conv_w = (const float*)d_in[7];
    const float* conv_b = (const float*)d_in[8];
    float* out = (float*)d_out;

    cudaFuncSetAttribute(k_conv, cudaFuncAttributeMaxDynamicSharedMemorySize, SM_SZ);
    k_pre<<<BB * NQ * 4, 256>>>(x, cw, qw, w1, b1, w2, b2, conv_b, out, out_size);
    k_conv<<<GRID_CONV, 512, SM_SZ>>>(x, conv_w, out);
}